// round 1
// baseline (speedup 1.0000x reference)
#include <cuda_runtime.h>
#include <math.h>

#define CC 32
#define TT 768
#define DD 100
#define HH 5
#define HIDG 60
#define FFND 64
#define NPREDK 10
#define LHID 200
#define NLAYER 3
#define CT (CC*TT)          // 24576
#define QKVW (3*HH*DD)      // 1500
#define HDW (HH*DD)         // 500

// ---------------- device scratch (static, no allocation) ----------------
__device__ float g_adj[CC*CC];
__device__ float g_h1[CT*DD];
__device__ float g_hid[CT*HIDG];
__device__ float g_hid2[CT*HIDG];
__device__ float g_x[CT*DD];
__device__ float g_y[CT*DD];
__device__ float g_ffn[CT*FFND];
__device__ float g_qkv[(size_t)CT*QKVW];
__device__ float g_att[(size_t)CT*HDW];
__device__ float g_wpack[DD*QKVW];
__device__ float g_M2[DD*DD];
__device__ float g_cvec[DD];
__device__ float g_carryA[CC*DD];
__device__ float g_carryB[CC*DD];

// ---------------- adjacency normalization ----------------
__global__ void k_adj(const float* __restrict__ A){
    int i = threadIdx.x;
    if (i >= CC) return;
    float s = 0.f;
    for (int j = 0; j < CC; j++){
        float v = A[i*CC + j] + (i == j ? 1.f : 0.f);
        s += v;
    }
    float inv = 1.f / s;
    for (int j = 0; j < CC; j++){
        float v = A[i*CC + j] + (i == j ? 1.f : 0.f);
        g_adj[i*CC + j] = v * inv;
    }
}

// out[i, n] = sum_j adj[i,j] * in[j, n]   (n ranges over T*dim)
__global__ void k_agg(const float* __restrict__ in, float* __restrict__ out, int TD){
    int n = blockIdx.x * blockDim.x + threadIdx.x;
    int i = blockIdx.y;
    if (n >= TD) return;
    float acc = 0.f;
    #pragma unroll
    for (int j = 0; j < CC; j++)
        acc += g_adj[i*CC + j] * in[(size_t)j*TD + n];
    out[(size_t)i*TD + n] = acc;
}

// ---------------- generic tiled SGEMM: C = act(A@B + bias + R) ----------------
// BM=BN=64, BK=16, 256 threads, 4x4 micro-tile
template<int RELU, int HASB, int HASR>
__global__ void __launch_bounds__(256)
k_gemm(const float* __restrict__ A, const float* __restrict__ B,
       const float* __restrict__ bias, const float* __restrict__ R,
       float* __restrict__ C, int M, int N, int K){
    __shared__ __align__(16) float As[16][64];
    __shared__ __align__(16) float Bs[16][64];
    int tid = threadIdx.x;
    int tx = tid & 15, ty = tid >> 4;
    int m0 = blockIdx.y * 64, n0 = blockIdx.x * 64;
    float acc[4][4] = {};
    int nk = (K + 15) >> 4;
    for (int kt = 0; kt < nk; kt++){
        int k0 = kt * 16;
        {
            int r = tid >> 2; int kc = (tid & 3) * 4;
            int grow = m0 + r;
            #pragma unroll
            for (int i = 0; i < 4; i++){
                int kk = k0 + kc + i;
                As[kc + i][r] = (grow < M && kk < K) ? A[(size_t)grow*K + kk] : 0.f;
            }
        }
        {
            int kr = tid >> 4; int nc = (tid & 15) * 4;
            int gk = k0 + kr;
            #pragma unroll
            for (int i = 0; i < 4; i++){
                int gn = n0 + nc + i;
                Bs[kr][nc + i] = (gk < K && gn < N) ? B[(size_t)gk*N + gn] : 0.f;
            }
        }
        __syncthreads();
        #pragma unroll
        for (int kc = 0; kc < 16; kc++){
            float4 a4 = *(const float4*)&As[kc][ty*4];
            float4 b4 = *(const float4*)&Bs[kc][tx*4];
            float av[4] = {a4.x, a4.y, a4.z, a4.w};
            float bv[4] = {b4.x, b4.y, b4.z, b4.w};
            #pragma unroll
            for (int j = 0; j < 4; j++)
                #pragma unroll
                for (int i = 0; i < 4; i++)
                    acc[j][i] += av[j] * bv[i];
        }
        __syncthreads();
    }
    #pragma unroll
    for (int j = 0; j < 4; j++){
        int row = m0 + ty*4 + j;
        if (row >= M) continue;
        #pragma unroll
        for (int i = 0; i < 4; i++){
            int col = n0 + tx*4 + i;
            if (col >= N) continue;
            float v = acc[j][i];
            if (HASB) v += bias[col];
            if (HASR) v += R[(size_t)row*N + col];
            if (RELU) v = fmaxf(v, 0.f);
            C[(size_t)row*N + col] = v;
        }
    }
}

// ---------------- pack QKV weights for layer l: [100 x 1500] ----------------
__global__ void k_pack(const float* __restrict__ wq, const float* __restrict__ wk,
                       const float* __restrict__ wv, int l){
    int idx = blockIdx.x * blockDim.x + threadIdx.x;
    if (idx >= DD*QKVW) return;
    int k = idx / QKVW;
    int n = idx % QKVW;
    int type = n / HDW;
    int rem = n % HDW;
    int h = rem / DD, e = rem % DD;
    const float* w = (type == 0) ? wq : (type == 1 ? wk : wv);
    g_wpack[idx] = w[(((size_t)l*HH + h)*DD + k)*DD + e];
}

// ---------------- fused flash attention ----------------
// grid (T/64, H, C), 256 threads (16x16). qkv rows: [q(500)|k(500)|v(500)]
#define BQ 64
#define BK 64
#define QS 68     // stride of d-major Q/K tiles and of Ps rows
#define VSR 132   // stride of Vs rows (padded d to 128)
#define DP 128
#define ATT_SMEM_FLOATS (DD*QS + DD*QS + BK*VSR + BQ*QS + 3*BQ)

__global__ void __launch_bounds__(256)
k_attn(const float* __restrict__ qkv, float* __restrict__ att){
    extern __shared__ __align__(16) float sm[];
    float* Qs  = sm;                    // [d][q], d<100
    float* Ks  = Qs + DD*QS;            // [d][k]
    float* Vs  = Ks + DD*QS;            // [k][d], d padded to 128
    float* Ps  = Vs + BK*VSR;           // [q][k]
    float* smm = Ps + BQ*QS;
    float* sml = smm + BQ;
    float* sma = sml + BQ;

    int tid = threadIdx.x;
    int tx = tid & 15, ty = tid >> 4;
    int qt = blockIdx.x, h = blockIdx.y, c = blockIdx.z;

    const float* Qg = qkv + (size_t)c*TT*QKVW + h*DD;
    const float* Kg = Qg + HDW;
    const float* Vg = Qg + 2*HDW;

    for (int idx = tid; idx < BQ*DD; idx += 256){
        int q = idx / DD, d = idx % DD;
        Qs[d*QS + q] = Qg[(size_t)(qt*BQ + q)*QKVW + d];
    }
    if (tid < BQ){ smm[tid] = -1e30f; sml[tid] = 0.f; }

    float o[4][8];
    #pragma unroll
    for (int j = 0; j < 4; j++)
        #pragma unroll
        for (int i = 0; i < 8; i++) o[j][i] = 0.f;

    for (int kt = 0; kt < TT/BK; kt++){
        __syncthreads();   // prev PV done; Q load visible
        for (int idx = tid; idx < BK*DD; idx += 256){
            int k = idx / DD, d = idx % DD;
            Ks[d*QS + k] = Kg[(size_t)(kt*BK + k)*QKVW + d];
        }
        for (int idx = tid; idx < BK*DP; idx += 256){
            int k = idx / DP, d = idx % DP;
            Vs[k*VSR + d] = (d < DD) ? Vg[(size_t)(kt*BK + k)*QKVW + d] : 0.f;
        }
        __syncthreads();

        // S = Q @ K^T  (4x4 per thread)
        float acc[4][4] = {};
        #pragma unroll 2
        for (int d = 0; d < DD; d++){
            float4 a4 = *(const float4*)&Qs[d*QS + ty*4];
            float4 b4 = *(const float4*)&Ks[d*QS + tx*4];
            float av[4] = {a4.x, a4.y, a4.z, a4.w};
            float bv[4] = {b4.x, b4.y, b4.z, b4.w};
            #pragma unroll
            for (int j = 0; j < 4; j++)
                #pragma unroll
                for (int i = 0; i < 4; i++)
                    acc[j][i] += av[j] * bv[i];
        }
        #pragma unroll
        for (int j = 0; j < 4; j++){
            float4 w = make_float4(acc[j][0]*0.1f, acc[j][1]*0.1f,
                                   acc[j][2]*0.1f, acc[j][3]*0.1f);
            *(float4*)&Ps[(ty*4 + j)*QS + tx*4] = w;
        }
        __syncthreads();

        // online softmax: 4 threads per row
        {
            int q = tid >> 2, part = tid & 3;
            int kb = part * 16;
            float mloc = -1e30f;
            #pragma unroll
            for (int kk = 0; kk < 16; kk++)
                mloc = fmaxf(mloc, Ps[q*QS + kb + kk]);
            mloc = fmaxf(mloc, __shfl_xor_sync(0xffffffffu, mloc, 1));
            mloc = fmaxf(mloc, __shfl_xor_sync(0xffffffffu, mloc, 2));
            float mOld = smm[q];
            float mNew = fmaxf(mOld, mloc);
            float alpha = __expf(mOld - mNew);
            float ls = 0.f;
            #pragma unroll
            for (int kk = 0; kk < 16; kk++){
                float p = __expf(Ps[q*QS + kb + kk] - mNew);
                Ps[q*QS + kb + kk] = p;
                ls += p;
            }
            ls += __shfl_xor_sync(0xffffffffu, ls, 1);
            ls += __shfl_xor_sync(0xffffffffu, ls, 2);
            __syncwarp();
            if (part == 0){
                smm[q] = mNew;
                sml[q] = sml[q]*alpha + ls;
                sma[q] = alpha;
            }
        }
        __syncthreads();

        // rescale O, then O += P @ V  (4x8 per thread)
        float al[4];
        #pragma unroll
        for (int j = 0; j < 4; j++) al[j] = sma[ty*4 + j];
        #pragma unroll
        for (int j = 0; j < 4; j++)
            #pragma unroll
            for (int i = 0; i < 8; i++) o[j][i] *= al[j];

        #pragma unroll 2
        for (int kk = 0; kk < BK; kk++){
            float a0 = Ps[(ty*4 + 0)*QS + kk];
            float a1 = Ps[(ty*4 + 1)*QS + kk];
            float a2 = Ps[(ty*4 + 2)*QS + kk];
            float a3 = Ps[(ty*4 + 3)*QS + kk];
            float4 b0 = *(const float4*)&Vs[kk*VSR + tx*4];
            float4 b1 = *(const float4*)&Vs[kk*VSR + 64 + tx*4];
            float av[4] = {a0, a1, a2, a3};
            float bv[8] = {b0.x, b0.y, b0.z, b0.w, b1.x, b1.y, b1.z, b1.w};
            #pragma unroll
            for (int j = 0; j < 4; j++)
                #pragma unroll
                for (int i = 0; i < 8; i++)
                    o[j][i] += av[j] * bv[i];
        }
    }
    __syncthreads();
    float linv[4];
    #pragma unroll
    for (int j = 0; j < 4; j++) linv[j] = 1.f / sml[ty*4 + j];
    #pragma unroll
    for (int j = 0; j < 4; j++){
        int q = qt*BQ + ty*4 + j;
        float* orow = att + ((size_t)c*TT + q)*HDW + h*DD;
        #pragma unroll
        for (int i = 0; i < 8; i++){
            int d = (i < 4) ? tx*4 + i : 64 + tx*4 + (i - 4);
            if (d < DD) orow[d] = o[j][i] * linv[j];
        }
    }
}

// ---------------- layernorm, in place, warp per row ----------------
__global__ void k_ln(float* __restrict__ x, const float* __restrict__ g,
                     const float* __restrict__ b){
    int warp = threadIdx.x >> 5;
    int lane = threadIdx.x & 31;
    int row = blockIdx.x * 8 + warp;
    if (row >= CT) return;
    float* xr = x + (size_t)row*DD;
    float v0 = xr[lane], v1 = xr[lane+32], v2 = xr[lane+64];
    float v3 = (lane + 96 < DD) ? xr[lane+96] : 0.f;
    float s = v0 + v1 + v2 + v3;
    #pragma unroll
    for (int o = 16; o; o >>= 1) s += __shfl_xor_sync(0xffffffffu, s, o);
    float mean = s * (1.f/DD);
    float d0 = v0-mean, d1 = v1-mean, d2 = v2-mean;
    float d3 = (lane + 96 < DD) ? (v3 - mean) : 0.f;
    float vs = d0*d0 + d1*d1 + d2*d2 + d3*d3;
    #pragma unroll
    for (int o = 16; o; o >>= 1) vs += __shfl_xor_sync(0xffffffffu, vs, o);
    float inv = rsqrtf(vs * (1.f/DD) + 1e-5f);
    xr[lane]      = d0*inv*g[lane]      + b[lane];
    xr[lane+32]   = d1*inv*g[lane+32]   + b[lane+32];
    xr[lane+64]   = d2*inv*g[lane+64]   + b[lane+64];
    if (lane + 96 < DD) xr[lane+96] = d3*inv*g[lane+96] + b[lane+96];
}

// ---------------- prediction head: fold affine step ----------------
__global__ void k_stepM(const float* __restrict__ l1, const float* __restrict__ l1b,
                        const float* __restrict__ l2, const float* __restrict__ l2b){
    int idx = blockIdx.x * blockDim.x + threadIdx.x;
    if (idx < DD*DD){
        int e = idx / DD, d = idx % DD;
        float acc = 0.f;
        for (int r = 0; r < LHID; r++)
            acc += l1[e*LHID + r] * l2[r*DD + d];
        g_M2[idx] = acc;
    } else if (idx < DD*DD + DD){
        int d = idx - DD*DD;
        float acc = l2b[d];
        for (int r = 0; r < LHID; r++)
            acc += l1b[r] * l2[r*DD + d];
        g_cvec[d] = acc;
    }
}

__global__ void k_step(const float* __restrict__ carry, int rstride,
                       float* __restrict__ out, float* __restrict__ nxt, int kidx){
    int idx = blockIdx.x * blockDim.x + threadIdx.x;
    if (idx >= CC*DD) return;
    int c = idx / DD, d = idx % DD;
    const float* cr = carry + (size_t)c*rstride;
    float acc = g_cvec[d];
    #pragma unroll 4
    for (int e = 0; e < DD; e++)
        acc += cr[e] * g_M2[e*DD + d];
    out[((size_t)c*NPREDK + kidx)*DD + d] = acc;
    nxt[c*DD + d] = acc;
}

// ---------------- host orchestration ----------------
static float* sym(const void* s){
    void* p = nullptr;
    cudaGetSymbolAddress(&p, s);
    return (float*)p;
}

extern "C" void kernel_launch(void* const* d_in, const int* in_sizes, int n_in,
                              void* d_out, int out_size){
    const float* X      = (const float*)d_in[0];
    const float* A      = (const float*)d_in[1];
    const float* gcn_w1 = (const float*)d_in[2];
    const float* gcn_b1 = (const float*)d_in[3];
    const float* gcn_w2 = (const float*)d_in[4];
    const float* gcn_b2 = (const float*)d_in[5];
    const float* enc_wq = (const float*)d_in[6];
    const float* enc_wk = (const float*)d_in[7];
    const float* enc_wv = (const float*)d_in[8];
    const float* enc_wm = (const float*)d_in[9];
    const float* enc_f1w= (const float*)d_in[10];
    const float* enc_f1b= (const float*)d_in[11];
    const float* enc_f2w= (const float*)d_in[12];
    const float* enc_f2b= (const float*)d_in[13];
    const float* ln1g   = (const float*)d_in[14];
    const float* ln1b   = (const float*)d_in[15];
    const float* ln2g   = (const float*)d_in[16];
    const float* ln2b   = (const float*)d_in[17];
    const float* lin1_w = (const float*)d_in[18];
    const float* lin1_b = (const float*)d_in[19];
    const float* lin2_w = (const float*)d_in[20];
    const float* lin2_b = (const float*)d_in[21];
    float* out = (float*)d_out;

    float* p_h1   = sym(g_h1);
    float* p_hid  = sym(g_hid);
    float* p_hid2 = sym(g_hid2);
    float* p_x    = sym(g_x);
    float* p_y    = sym(g_y);
    float* p_ffn  = sym(g_ffn);
    float* p_qkv  = sym(g_qkv);
    float* p_att  = sym(g_att);
    float* p_wp   = sym(g_wpack);
    float* p_cA   = sym(g_carryA);
    float* p_cB   = sym(g_carryB);

    const int ATT_SMEM = ATT_SMEM_FLOATS * (int)sizeof(float);
    cudaFuncSetAttribute(k_attn, cudaFuncAttributeMaxDynamicSharedMemorySize, ATT_SMEM);

    // GCN
    k_adj<<<1, 32>>>(A);
    k_agg<<<dim3((TT*DD + 255)/256, CC), 256>>>(X, p_h1, TT*DD);
    k_gemm<1,1,0><<<dim3(1, CT/64), 256>>>(p_h1, gcn_w1, gcn_b1, nullptr, p_hid, CT, HIDG, DD);
    k_agg<<<dim3((TT*HIDG + 255)/256, CC), 256>>>(p_hid, p_hid2, TT*HIDG);
    k_gemm<0,1,0><<<dim3(2, CT/64), 256>>>(p_hid2, gcn_w2, gcn_b2, nullptr, p_x, CT, DD, HIDG);

    // Encoder layers
    for (int l = 0; l < NLAYER; l++){
        k_pack<<<(DD*QKVW + 255)/256, 256>>>(enc_wq, enc_wk, enc_wv, l);
        k_gemm<0,0,0><<<dim3((QKVW + 63)/64, CT/64), 256>>>(p_x, p_wp, nullptr, nullptr, p_qkv, CT, QKVW, DD);
        k_attn<<<dim3(TT/BQ, HH, CC), 256, ATT_SMEM>>>(p_qkv, p_att);
        k_gemm<0,0,1><<<dim3(2, CT/64), 256>>>(p_att, enc_wm + (size_t)l*HDW*DD, nullptr, p_x, p_y, CT, DD, HDW);
        k_ln<<<CT/8, 256>>>(p_y, ln1g + l*DD, ln1b + l*DD);
        k_gemm<1,1,0><<<dim3(1, CT/64), 256>>>(p_y, enc_f1w + (size_t)l*DD*FFND, enc_f1b + l*FFND, nullptr, p_ffn, CT, FFND, DD);
        k_gemm<0,1,1><<<dim3(2, CT/64), 256>>>(p_ffn, enc_f2w + (size_t)l*FFND*DD, enc_f2b + l*DD, p_y, p_x, CT, DD, FFND);
        k_ln<<<CT/8, 256>>>(p_x, ln2g + l*DD, ln2b + l*DD);
    }

    // Head: fold (W1,b1,W2,b2) into affine map (M2, cvec), then 10 steps
    k_stepM<<<(DD*DD + DD + 255)/256, 256>>>(lin1_w, lin1_b, lin2_w, lin2_b);
    const float* carry = p_x + (size_t)(TT - 1)*DD;   // h[:, -1, :] with row stride T*D
    int rs = TT*DD;
    for (int k = 0; k < NPREDK; k++){
        float* nxt = (k & 1) ? p_cB : p_cA;
        k_step<<<(CC*DD + 255)/256, 256>>>(carry, rs, out, nxt, k);
        carry = nxt;
        rs = DD;
    }
}

// round 4
// speedup vs baseline: 4.7830x; 4.7830x over previous
#include <cuda_runtime.h>
#include <cuda_fp16.h>
#include <math.h>

#define CC 32
#define TT 768
#define DD 100
#define HH 5
#define HIDG 60
#define FFND 64
#define NPREDK 10
#define LHID 200
#define NLAYER 3
#define CT (CC*TT)          // 24576
#define DP 128              // padded feature/head dim
#define QKVP (15*DP)        // 1920: [q h0..h4 | k h0..h4 | v h0..h4] x 128
#define ATTP (HH*DP)        // 640
#define NB (CC*HH)          // 160

// ---------------- device scratch ----------------
__device__ float g_adj[CC*CC];
__device__ float g_h1[CT*DD];
__device__ float g_hid[CT*HIDG];
__device__ float g_hid2[CT*HIDG];
__device__ float g_x[CT*DD];
__device__ float g_y[CT*DD];
__device__ float g_M2[DD*DD];
__device__ float g_cvec[DD];
__device__ float g_carryA[CC*DD];
__device__ float g_carryB[CC*DD];
__device__ float g_rs[NB*TT];

__device__ __half g_xh[CT*DP];
__device__ __half g_qkvh[(size_t)CT*QKVP];
__device__ __half g_atth[(size_t)CT*ATTP];   // pad cols stay zero (.bss)
__device__ __half g_P[(size_t)NB*TT*TT];
__device__ __half g_ffnh[CT*FFND];
__device__ __half g_wqkv[NLAYER*DP*QKVP];
__device__ __half g_wm[NLAYER*ATTP*DP];
__device__ __half g_f1[NLAYER*DP*FFND];
__device__ __half g_f2[NLAYER*FFND*DP];

// ---------------- small helpers ----------------
__device__ __forceinline__ unsigned sptr(const void* p){
    return (unsigned)__cvta_generic_to_shared(p);
}
__device__ __forceinline__ void cpa16(unsigned dst, const void* src, int bytes){
    asm volatile("cp.async.cg.shared.global [%0], [%1], 16, %2;\n"
                 :: "r"(dst), "l"(src), "r"(bytes));
}
__device__ __forceinline__ void cp_commit(){ asm volatile("cp.async.commit_group;\n" ::: "memory"); }
__device__ __forceinline__ void cp_wait0(){ asm volatile("cp.async.wait_group 0;\n" ::: "memory"); }

__device__ __forceinline__ void ldsm4(unsigned& r0,unsigned& r1,unsigned& r2,unsigned& r3, unsigned a){
    asm volatile("ldmatrix.sync.aligned.m8n8.x4.shared.b16 {%0,%1,%2,%3}, [%4];\n"
        : "=r"(r0),"=r"(r1),"=r"(r2),"=r"(r3) : "r"(a));
}
__device__ __forceinline__ void ldsm4t(unsigned& r0,unsigned& r1,unsigned& r2,unsigned& r3, unsigned a){
    asm volatile("ldmatrix.sync.aligned.m8n8.x4.trans.shared.b16 {%0,%1,%2,%3}, [%4];\n"
        : "=r"(r0),"=r"(r1),"=r"(r2),"=r"(r3) : "r"(a));
}
__device__ __forceinline__ void mma16816(float* c, const unsigned* a, const unsigned* b){
    asm volatile("mma.sync.aligned.m16n8k16.row.col.f32.f16.f16.f32 "
        "{%0,%1,%2,%3}, {%4,%5,%6,%7}, {%8,%9}, {%0,%1,%2,%3};\n"
        : "+f"(c[0]),"+f"(c[1]),"+f"(c[2]),"+f"(c[3])
        : "r"(a[0]),"r"(a[1]),"r"(a[2]),"r"(a[3]), "r"(b[0]),"r"(b[1]));
}

// ---------------- fp16 tensor-core GEMM ----------------
// C[M,N] = epi(A[M,K] @ B), fp32 accum. TRANSB=0: B[K,N] row-major; TRANSB=1: B[N,K] row-major.
// M % 128 == 0 and K % 32 == 0 are guaranteed by construction (padded buffers).
// EPI: 0 half(acc); 1 half(exp(0.1*acc)); 2 half(acc/rs[row]); 3 f32 acc+res;
//      4 half(relu(acc+bias)); 5 f32 acc+bias+res
#define BM 128
#define BN 64
#define BKK 32

template<int TRANSB, int EPI>
__global__ void __launch_bounds__(256)
hgemm(const __half* __restrict__ A, const __half* __restrict__ B,
      float* __restrict__ outF, __half* __restrict__ outH,
      const float* __restrict__ bias, const float* __restrict__ res, int ldr,
      const float* __restrict__ rs,
      int M, int N, int K, int lda, int ldb, int ldc,
      int zdiv, size_t sA1, size_t sA2, size_t sB1, size_t sB2, size_t sC1, size_t sC2)
{
    constexpr int BROW = TRANSB ? BN : BKK;
    constexpr int BCOL = TRANSB ? (BKK+8) : (BN+8);
    __shared__ __align__(16) __half As[2][BM][BKK+8];
    __shared__ __align__(16) __half Bs[2][BROW][BCOL];

    int z = blockIdx.z;
    int zq = z / zdiv, zr = z % zdiv;
    A += zq*sA1 + zr*sA2;
    B += zq*sB1 + zr*sB2;
    size_t coff = zq*sC1 + zr*sC2;
    if (EPI == 2) rs += (size_t)z * M;

    int tid = threadIdx.x;
    int m0 = blockIdx.y * BM, n0 = blockIdx.x * BN;
    int warp = tid >> 5, lane = tid & 31;
    int wm0 = (warp >> 1) * 32, wn0 = (warp & 1) * 32;

    float c[2][4][4];
    #pragma unroll
    for (int a=0;a<2;a++) for (int b=0;b<4;b++) for (int d=0;d<4;d++) c[a][b][d]=0.f;

    auto prefA = [&](int kt, int buf){
        int k0 = kt*BKK;
        #pragma unroll
        for (int i=0;i<2;i++){
            int q = tid + i*256;
            int r = q >> 2, cc = (q & 3) * 8;
            cpa16(sptr(&As[buf][r][cc]), A + (size_t)(m0+r)*lda + k0 + cc, 16);
        }
    };
    auto prefB = [&](int kt, int buf){
        int k0 = kt*BKK;
        if (TRANSB){
            int r = tid >> 2, cc = (tid & 3) * 8;
            int bytes = (n0 + r < N) ? 16 : 0;
            const __half* src = bytes ? (B + (size_t)(n0+r)*ldb + k0 + cc) : B;
            cpa16(sptr(&Bs[buf][r][cc]), src, bytes);
        } else {
            int r = tid >> 3, cc = (tid & 7) * 8;
            int nrem = N - (n0 + cc);
            int bytes = nrem >= 8 ? 16 : (nrem > 0 ? nrem*2 : 0);
            const __half* src = bytes ? (B + (size_t)(k0+r)*ldb + n0 + cc) : B;
            cpa16(sptr(&Bs[buf][r][cc]), src, bytes);
        }
    };

    int nk = K / BKK;
    prefA(0,0); prefB(0,0); cp_commit();

    for (int kt = 0; kt < nk; kt++){
        int buf = kt & 1;
        cp_wait0();
        __syncthreads();
        if (kt+1 < nk){ prefA(kt+1, buf^1); prefB(kt+1, buf^1); }
        cp_commit();

        #pragma unroll
        for (int ks = 0; ks < 2; ks++){
            unsigned a[2][4], b[4][2];
            #pragma unroll
            for (int mt = 0; mt < 2; mt++){
                unsigned ad = sptr(&As[buf][wm0 + mt*16 + (lane & 15)][ks*16 + (lane >> 4)*8]);
                ldsm4(a[mt][0], a[mt][1], a[mt][2], a[mt][3], ad);
            }
            #pragma unroll
            for (int np = 0; np < 2; np++){
                if (TRANSB){
                    unsigned ad = sptr(&Bs[buf][wn0 + np*16 + (lane & 7) + ((lane >> 4) << 3)]
                                               [ks*16 + ((lane >> 3) & 1)*8]);
                    ldsm4(b[np*2][0], b[np*2][1], b[np*2+1][0], b[np*2+1][1], ad);
                } else {
                    unsigned ad = sptr(&Bs[buf][ks*16 + (lane & 15)][wn0 + np*16 + (lane >> 4)*8]);
                    ldsm4t(b[np*2][0], b[np*2][1], b[np*2+1][0], b[np*2+1][1], ad);
                }
            }
            #pragma unroll
            for (int mt = 0; mt < 2; mt++)
                #pragma unroll
                for (int nt = 0; nt < 4; nt++)
                    mma16816(c[mt][nt], a[mt], b[nt]);
        }
        __syncthreads();
    }

    // epilogue
    #pragma unroll
    for (int mt = 0; mt < 2; mt++){
        #pragma unroll
        for (int i = 0; i < 2; i++){
            int row = m0 + wm0 + mt*16 + (lane >> 2) + i*8;
            float rinv = 0.f;
            if (EPI == 2) rinv = 1.f / rs[row];
            #pragma unroll
            for (int nt = 0; nt < 4; nt++){
                int col = n0 + wn0 + nt*8 + (lane & 3)*2;
                if (col >= N) continue;
                float v0 = c[mt][nt][i*2+0];
                float v1 = c[mt][nt][i*2+1];
                size_t off = coff + (size_t)row*ldc + col;
                if (EPI == 0){
                    *(__half2*)(outH + off) = __floats2half2_rn(v0, v1);
                } else if (EPI == 1){
                    *(__half2*)(outH + off) = __floats2half2_rn(__expf(v0*0.1f), __expf(v1*0.1f));
                } else if (EPI == 2){
                    *(__half2*)(outH + off) = __floats2half2_rn(v0*rinv, v1*rinv);
                } else if (EPI == 3){
                    outF[off]   = v0 + res[(size_t)row*ldr + col];
                    outF[off+1] = v1 + res[(size_t)row*ldr + col + 1];
                } else if (EPI == 4){
                    *(__half2*)(outH + off) = __floats2half2_rn(fmaxf(v0 + bias[col], 0.f),
                                                                fmaxf(v1 + bias[col+1], 0.f));
                } else if (EPI == 5){
                    outF[off]   = v0 + bias[col]   + res[(size_t)row*ldr + col];
                    outF[off+1] = v1 + bias[col+1] + res[(size_t)row*ldr + col + 1];
                }
            }
        }
    }
}

// ---------------- P row sums ----------------
__global__ void k_rsum(const __half* __restrict__ P, float* __restrict__ rs){
    int row = blockIdx.x*8 + (threadIdx.x >> 5);
    int lane = threadIdx.x & 31;
    const __half* pr = P + (size_t)row*TT;
    float s = 0.f;
    #pragma unroll
    for (int j = 0; j < 3; j++){
        float4 f4 = *(const float4*)(pr + j*256 + lane*8);
        const __half2* h2 = (const __half2*)&f4;
        #pragma unroll
        for (int q = 0; q < 4; q++){ float2 fp = __half22float2(h2[q]); s += fp.x + fp.y; }
    }
    #pragma unroll
    for (int o = 16; o; o >>= 1) s += __shfl_xor_sync(0xffffffffu, s, o);
    if (!lane) rs[row] = s;
}

// ---------------- conversions / packing ----------------
__global__ void k_h16(const float* __restrict__ x, __half* __restrict__ xh){
    int idx = blockIdx.x*256 + threadIdx.x;
    if (idx >= CT*DP) return;
    int row = idx / DP, col = idx % DP;
    xh[idx] = __float2half(col < DD ? x[row*DD + col] : 0.f);
}

__global__ void k_pack_qkv(const float* __restrict__ wq, const float* __restrict__ wk,
                           const float* __restrict__ wv){
    int idx = blockIdx.x*256 + threadIdx.x;
    if (idx >= NLAYER*DP*QKVP) return;
    int l = idx / (DP*QKVP);
    int r = idx % (DP*QKVP);
    int k = r / QKVP, n = r % QKVP;
    int slot = n / DP, d = n % DP;
    int type = slot / HH, h = slot % HH;
    float v = 0.f;
    if (k < DD && d < DD){
        const float* w = type == 0 ? wq : (type == 1 ? wk : wv);
        v = w[(((size_t)l*HH + h)*DD + k)*DD + d];
    }
    g_wqkv[idx] = __float2half(v);
}

__global__ void k_pack_wm(const float* __restrict__ wm){
    int idx = blockIdx.x*256 + threadIdx.x;
    if (idx >= NLAYER*ATTP*DP) return;
    int l = idx / (ATTP*DP);
    int r = idx % (ATTP*DP);
    int k = r / DP, n = r % DP;
    int h = k / DP, dk = k % DP;
    float v = 0.f;
    if (dk < DD && n < DD)
        v = wm[((size_t)l*(HH*DD) + h*DD + dk)*DD + n];
    g_wm[idx] = __float2half(v);
}

__global__ void k_pack_f1(const float* __restrict__ f1){
    int idx = blockIdx.x*256 + threadIdx.x;
    if (idx >= NLAYER*DP*FFND) return;
    int l = idx / (DP*FFND);
    int r = idx % (DP*FFND);
    int k = r / FFND, n = r % FFND;
    g_f1[idx] = __float2half(k < DD ? f1[((size_t)l*DD + k)*FFND + n] : 0.f);
}

__global__ void k_pack_f2(const float* __restrict__ f2){
    int idx = blockIdx.x*256 + threadIdx.x;
    if (idx >= NLAYER*FFND*DP) return;
    int l = idx / (FFND*DP);
    int r = idx % (FFND*DP);
    int k = r / DP, n = r % DP;
    g_f2[idx] = __float2half(n < DD ? f2[((size_t)l*FFND + k)*DD + n] : 0.f);
}

// ---------------- layernorm (fp32 in-place) + fp16 padded output ----------------
__global__ void k_lnh(float* __restrict__ x, const float* __restrict__ g,
                      const float* __restrict__ b, __half* __restrict__ xh){
    int warp = threadIdx.x >> 5;
    int lane = threadIdx.x & 31;
    int row = blockIdx.x*8 + warp;
    if (row >= CT) return;
    float* xr = x + (size_t)row*DD;
    float v0 = xr[lane], v1 = xr[lane+32], v2 = xr[lane+64];
    float v3 = (lane + 96 < DD) ? xr[lane+96] : 0.f;
    float s = v0 + v1 + v2 + v3;
    #pragma unroll
    for (int o = 16; o; o >>= 1) s += __shfl_xor_sync(0xffffffffu, s, o);
    float mean = s * (1.f/DD);
    float d0 = v0-mean, d1 = v1-mean, d2 = v2-mean;
    float d3 = (lane + 96 < DD) ? (v3 - mean) : 0.f;
    float vs = d0*d0 + d1*d1 + d2*d2 + d3*d3;
    #pragma unroll
    for (int o = 16; o; o >>= 1) vs += __shfl_xor_sync(0xffffffffu, vs, o);
    float inv = rsqrtf(vs * (1.f/DD) + 1e-5f);
    __half* hr = xh + (size_t)row*DP;
    float w;
    w = d0*inv*g[lane]    + b[lane];    xr[lane]    = w; hr[lane]    = __float2half(w);
    w = d1*inv*g[lane+32] + b[lane+32]; xr[lane+32] = w; hr[lane+32] = __float2half(w);
    w = d2*inv*g[lane+64] + b[lane+64]; xr[lane+64] = w; hr[lane+64] = __float2half(w);
    if (lane + 96 < DD){
        w = d3*inv*g[lane+96] + b[lane+96]; xr[lane+96] = w; hr[lane+96] = __float2half(w);
    } else {
        hr[96 + lane] = __half(0.f);   // cols 100..127 zero
    }
}

// ---------------- GCN (fp32, cheap) ----------------
__global__ void k_adj(const float* __restrict__ A){
    int i = threadIdx.x;
    if (i >= CC) return;
    float s = 0.f;
    for (int j = 0; j < CC; j++) s += A[i*CC + j] + (i == j ? 1.f : 0.f);
    float inv = 1.f / s;
    for (int j = 0; j < CC; j++)
        g_adj[i*CC + j] = (A[i*CC + j] + (i == j ? 1.f : 0.f)) * inv;
}

__global__ void k_agg(const float* __restrict__ in, float* __restrict__ out, int TD){
    int n = blockIdx.x * blockDim.x + threadIdx.x;
    int i = blockIdx.y;
    if (n >= TD) return;
    float acc = 0.f;
    #pragma unroll
    for (int j = 0; j < CC; j++)
        acc += g_adj[i*CC + j] * in[(size_t)j*TD + n];
    out[(size_t)i*TD + n] = acc;
}

template<int RELU, int HASB>
__global__ void __launch_bounds__(256)
k_gemm(const float* __restrict__ A, const float* __restrict__ B,
       const float* __restrict__ bias, float* __restrict__ C, int M, int N, int K){
    __shared__ __align__(16) float As[16][64];
    __shared__ __align__(16) float Bs[16][64];
    int tid = threadIdx.x;
    int tx = tid & 15, ty = tid >> 4;
    int m0 = blockIdx.y * 64, n0 = blockIdx.x * 64;
    float acc[4][4] = {};
    int nk = (K + 15) >> 4;
    for (int kt = 0; kt < nk; kt++){
        int k0 = kt * 16;
        {
            int r = tid >> 2; int kc = (tid & 3) * 4;
            int grow = m0 + r;
            #pragma unroll
            for (int i = 0; i < 4; i++){
                int kk = k0 + kc + i;
                As[kc + i][r] = (grow < M && kk < K) ? A[(size_t)grow*K + kk] : 0.f;
            }
        }
        {
            int kr = tid >> 4; int nc = (tid & 15) * 4;
            int gk = k0 + kr;
            #pragma unroll
            for (int i = 0; i < 4; i++){
                int gn = n0 + nc + i;
                Bs[kr][nc + i] = (gk < K && gn < N) ? B[(size_t)gk*N + gn] : 0.f;
            }
        }
        __syncthreads();
        #pragma unroll
        for (int kc = 0; kc < 16; kc++){
            float4 a4 = *(const float4*)&As[kc][ty*4];
            float4 b4 = *(const float4*)&Bs[kc][tx*4];
            float av[4] = {a4.x, a4.y, a4.z, a4.w};
            float bv[4] = {b4.x, b4.y, b4.z, b4.w};
            #pragma unroll
            for (int j = 0; j < 4; j++)
                #pragma unroll
                for (int i = 0; i < 4; i++)
                    acc[j][i] += av[j] * bv[i];
        }
        __syncthreads();
    }
    #pragma unroll
    for (int j = 0; j < 4; j++){
        int row = m0 + ty*4 + j;
        if (row >= M) continue;
        #pragma unroll
        for (int i = 0; i < 4; i++){
            int col = n0 + tx*4 + i;
            if (col >= N) continue;
            float v = acc[j][i];
            if (HASB) v += bias[col];
            if (RELU) v = fmaxf(v, 0.f);
            C[(size_t)row*N + col] = v;
        }
    }
}

// ---------------- prediction head ----------------
__global__ void k_stepM(const float* __restrict__ l1, const float* __restrict__ l1b,
                        const float* __restrict__ l2, const float* __restrict__ l2b){
    int idx = blockIdx.x * blockDim.x + threadIdx.x;
    if (idx < DD*DD){
        int e = idx / DD, d = idx % DD;
        float acc = 0.f;
        for (int r = 0; r < LHID; r++)
            acc += l1[e*LHID + r] * l2[r*DD + d];
        g_M2[idx] = acc;
    } else if (idx < DD*DD + DD){
        int d = idx - DD*DD;
        float acc = l2b[d];
        for (int r = 0; r < LHID; r++)
            acc += l1b[r] * l2[r*DD + d];
        g_cvec[d] = acc;
    }
}

__global__ void k_step(const float* __restrict__ carry, int rstride,
                       float* __restrict__ out, float* __restrict__ nxt, int kidx){
    int idx = blockIdx.x * blockDim.x + threadIdx.x;
    if (idx >= CC*DD) return;
    int c = idx / DD, d = idx % DD;
    const float* cr = carry + (size_t)c*rstride;
    float acc = g_cvec[d];
    #pragma unroll 4
    for (int e = 0; e < DD; e++)
        acc += cr[e] * g_M2[e*DD + d];
    out[((size_t)c*NPREDK + kidx)*DD + d] = acc;
    nxt[c*DD + d] = acc;
}

// ---------------- host orchestration ----------------
static float* symF(const void* s){ void* p = nullptr; cudaGetSymbolAddress(&p, s); return (float*)p; }
static __half* symH(const void* s){ void* p = nullptr; cudaGetSymbolAddress(&p, s); return (__half*)p; }

extern "C" void kernel_launch(void* const* d_in, const int* in_sizes, int n_in,
                              void* d_out, int out_size){
    const float* X      = (const float*)d_in[0];
    const float* A      = (const float*)d_in[1];
    const float* gcn_w1 = (const float*)d_in[2];
    const float* gcn_b1 = (const float*)d_in[3];
    const float* gcn_w2 = (const float*)d_in[4];
    const float* gcn_b2 = (const float*)d_in[5];
    const float* enc_wq = (const float*)d_in[6];
    const float* enc_wk = (const float*)d_in[7];
    const float* enc_wv = (const float*)d_in[8];
    const float* enc_wm = (const float*)d_in[9];
    const float* enc_f1w= (const float*)d_in[10];
    const float* enc_f1b= (const float*)d_in[11];
    const float* enc_f2w= (const float*)d_in[12];
    const float* enc_f2b= (const float*)d_in[13];
    const float* ln1g   = (const float*)d_in[14];
    const float* ln1b   = (const float*)d_in[15];
    const float* ln2g   = (const float*)d_in[16];
    const float* ln2b   = (const float*)d_in[17];
    const float* lin1_w = (const float*)d_in[18];
    const float* lin1_b = (const float*)d_in[19];
    const float* lin2_w = (const float*)d_in[20];
    const float* lin2_b = (const float*)d_in[21];
    float* out = (float*)d_out;

    float*  p_h1   = symF(g_h1);
    float*  p_hid  = symF(g_hid);
    float*  p_hid2 = symF(g_hid2);
    float*  p_x    = symF(g_x);
    float*  p_y    = symF(g_y);
    float*  p_rs   = symF(g_rs);
    float*  p_cA   = symF(g_carryA);
    float*  p_cB   = symF(g_carryB);
    __half* p_xh   = symH(g_xh);
    __half* p_qkv  = symH(g_qkvh);
    __half* p_att  = symH(g_atth);
    __half* p_P    = symH(g_P);
    __half* p_ffn  = symH(g_ffnh);
    __half* p_wqkv = symH(g_wqkv);
    __half* p_wm   = symH(g_wm);
    __half* p_f1   = symH(g_f1);
    __half* p_f2   = symH(g_f2);

    // GCN (fp32)
    k_adj<<<1, 32>>>(A);
    k_agg<<<dim3((TT*DD + 255)/256, CC), 256>>>(X, p_h1, TT*DD);
    k_gemm<1,1><<<dim3(1, CT/64), 256>>>(p_h1, gcn_w1, gcn_b1, p_hid, CT, HIDG, DD);
    k_agg<<<dim3((TT*HIDG + 255)/256, CC), 256>>>(p_hid, p_hid2, TT*HIDG);
    k_gemm<0,1><<<dim3(2, CT/64), 256>>>(p_hid2, gcn_w2, gcn_b2, p_x, CT, DD, HIDG);

    // pack all weights fp16 (all layers)
    k_pack_qkv<<<(NLAYER*DP*QKVP + 255)/256, 256>>>(enc_wq, enc_wk, enc_wv);
    k_pack_wm <<<(NLAYER*ATTP*DP + 255)/256, 256>>>(enc_wm);
    k_pack_f1 <<<(NLAYER*DP*FFND + 255)/256, 256>>>(enc_f1w);
    k_pack_f2 <<<(NLAYER*FFND*DP + 255)/256, 256>>>(enc_f2w);

    k_h16<<<(CT*DP + 255)/256, 256>>>(p_x, p_xh);

    for (int l = 0; l < NLAYER; l++){
        // QKV: [CT,128] @ [128,1920] -> fp16 qkvh
        hgemm<0,0><<<dim3(QKVP/BN, CT/BM, 1), 256>>>(
            p_xh, p_wqkv + (size_t)l*DP*QKVP, nullptr, p_qkv, nullptr, nullptr, 0, nullptr,
            CT, QKVP, DP, DP, QKVP, QKVP, 1, 0,0, 0,0, 0,0);

        // S = exp(0.1 * Q@K^T) per (c,h): batched, TRANSB
        hgemm<1,1><<<dim3(TT/BN, TT/BM, NB), 256>>>(
            p_qkv, p_qkv + HH*DP, nullptr, p_P, nullptr, nullptr, 0, nullptr,
            TT, TT, DP, QKVP, QKVP, TT, HH,
            (size_t)TT*QKVP, DP, (size_t)TT*QKVP, DP,
            (size_t)HH*TT*TT, (size_t)TT*TT);

        k_rsum<<<NB*TT/8, 256>>>(p_P, p_rs);

        // O = (P @ V) / rowsum  -> fp16 att (padded per head)
        hgemm<0,2><<<dim3(2, TT/BM, NB), 256>>>(
            p_P, p_qkv + 2*HH*DP, nullptr, p_att, nullptr, nullptr, 0, p_rs,
            TT, DD, TT, TT, QKVP, ATTP, HH,
            (size_t)HH*TT*TT, (size_t)TT*TT, (size_t)TT*QKVP, DP,
            (size_t)TT*ATTP, DP);

        // proj: y = x + att @ wm  (fp32 out)
        hgemm<0,3><<<dim3(2, CT/BM, 1), 256>>>(
            p_att, p_wm + (size_t)l*ATTP*DP, p_y, nullptr, nullptr, p_x, DD, nullptr,
            CT, DD, ATTP, ATTP, DP, DD, 1, 0,0, 0,0, 0,0);

        k_lnh<<<CT/8, 256>>>(p_y, ln1g + l*DD, ln1b + l*DD, p_xh);

        // ffn1: relu(xh @ f1 + b1) -> fp16
        hgemm<0,4><<<dim3(1, CT/BM, 1), 256>>>(
            p_xh, p_f1 + (size_t)l*DP*FFND, nullptr, p_ffn, enc_f1b + l*FFND, nullptr, 0, nullptr,
            CT, FFND, DP, DP, FFND, FFND, 1, 0,0, 0,0, 0,0);

        // ffn2: x = y + ffn @ f2 + b2 (fp32 out)
        hgemm<0,5><<<dim3(2, CT/BM, 1), 256>>>(
            p_ffn, p_f2 + (size_t)l*FFND*DP, p_x, nullptr, enc_f2b + l*DD, p_y, DD, nullptr,
            CT, DD, FFND, FFND, DP, DD, 1, 0,0, 0,0, 0,0);

        k_lnh<<<CT/8, 256>>>(p_x, ln2g + l*DD, ln2b + l*DD, p_xh);
    }

    // head: fold affine chain, iterate
    k_stepM<<<(DD*DD + DD + 255)/256, 256>>>(lin1_w, lin1_b, lin2_w, lin2_b);
    const float* carry = p_x + (size_t)(TT - 1)*DD;
    int rs = TT*DD;
    for (int k = 0; k < NPREDK; k++){
        float* nxt = (k & 1) ? p_cB : p_cA;
        k_step<<<(CC*DD + 255)/256, 256>>>(carry, rs, out, nxt, k);
        carry = nxt;
        rs = DD;
    }
}

// round 5
// speedup vs baseline: 6.5731x; 1.3743x over previous
#include <cuda_runtime.h>
#include <cuda_fp16.h>
#include <math.h>

#define CC 32
#define TT 768
#define DD 100
#define HH 5
#define HIDG 60
#define FFND 64
#define NPREDK 10
#define LHID 200
#define NLAYER 3
#define CT (CC*TT)          // 24576
#define DP 128              // padded feature/head dim
#define QKVP (15*DP)        // 1920
#define ATTP (HH*DP)        // 640
#define NB (CC*HH)          // 160

// ---------------- device scratch ----------------
__device__ float g_adj[CC*CC];
__device__ float g_h1[CT*DD];
__device__ float g_hid[CT*HIDG];
__device__ float g_hid2[CT*HIDG];
__device__ float g_x[CT*DD];
__device__ float g_y[CT*DD];
__device__ float g_M2[DD*DD];
__device__ float g_cvec[DD];
__device__ float g_carryA[CC*DD];
__device__ float g_carryB[CC*DD];

__device__ __half g_xh[CT*DP];
__device__ __half g_qkvh[(size_t)CT*QKVP];
__device__ __half g_atth[(size_t)CT*ATTP];   // pad cols stay zero (.bss)
__device__ __half g_ffnh[CT*FFND];
__device__ __half g_wqkv[NLAYER*DP*QKVP];
__device__ __half g_wm[NLAYER*ATTP*DP];
__device__ __half g_f1[NLAYER*DP*FFND];
__device__ __half g_f2[NLAYER*FFND*DP];

// ---------------- small helpers ----------------
__device__ __forceinline__ unsigned sptr(const void* p){
    return (unsigned)__cvta_generic_to_shared(p);
}
__device__ __forceinline__ void cpa16(unsigned dst, const void* src, int bytes){
    asm volatile("cp.async.cg.shared.global [%0], [%1], 16, %2;\n"
                 :: "r"(dst), "l"(src), "r"(bytes));
}
__device__ __forceinline__ void cp_commit(){ asm volatile("cp.async.commit_group;\n" ::: "memory"); }
__device__ __forceinline__ void cp_wait0(){ asm volatile("cp.async.wait_group 0;\n" ::: "memory"); }

__device__ __forceinline__ void ldsm4(unsigned& r0,unsigned& r1,unsigned& r2,unsigned& r3, unsigned a){
    asm volatile("ldmatrix.sync.aligned.m8n8.x4.shared.b16 {%0,%1,%2,%3}, [%4];\n"
        : "=r"(r0),"=r"(r1),"=r"(r2),"=r"(r3) : "r"(a));
}
__device__ __forceinline__ void ldsm4t(unsigned& r0,unsigned& r1,unsigned& r2,unsigned& r3, unsigned a){
    asm volatile("ldmatrix.sync.aligned.m8n8.x4.trans.shared.b16 {%0,%1,%2,%3}, [%4];\n"
        : "=r"(r0),"=r"(r1),"=r"(r2),"=r"(r3) : "r"(a));
}
__device__ __forceinline__ void mma16816(float* c, const unsigned* a, const unsigned* b){
    asm volatile("mma.sync.aligned.m16n8k16.row.col.f32.f16.f16.f32 "
        "{%0,%1,%2,%3}, {%4,%5,%6,%7}, {%8,%9}, {%0,%1,%2,%3};\n"
        : "+f"(c[0]),"+f"(c[1]),"+f"(c[2]),"+f"(c[3])
        : "r"(a[0]),"r"(a[1]),"r"(a[2]),"r"(a[3]), "r"(b[0]),"r"(b[1]));
}

// ---------------- fused flash attention (tensor cores) ----------------
// grid (TT/128, NB), 256 threads (8 warps, 16 q-rows each). O = softmax(Q Kt /10) V
#define FA_BQ 128
#define FA_BK 64
#define FA_DS 136
#define FA_SMEM ((FA_BQ + 4*FA_BK) * FA_DS * 2)   // Q + double-buffered K,V (bytes)

__global__ void __launch_bounds__(256, 1)
k_fattn(const __half* __restrict__ qkv, __half* __restrict__ att){
    extern __shared__ __align__(16) __half sm[];
    __half* Qs = sm;                       // [128][136]
    __half* Ks = Qs + FA_BQ*FA_DS;         // [2][64][136]
    __half* Vs = Ks + 2*FA_BK*FA_DS;       // [2][64][136]

    int tid = threadIdx.x, lane = tid & 31, w = tid >> 5;
    int qt = blockIdx.x;
    int z = blockIdx.y;
    int c = z / HH, h = z % HH;
    const __half* Qg = qkv + (size_t)c*TT*QKVP + h*DP;
    const __half* Kg = Qg + HH*DP;
    const __half* Vg = Qg + 2*HH*DP;

    // Q tile -> smem (128x128 halves)
    #pragma unroll
    for (int i = 0; i < 8; i++){
        int idx = tid + i*256;
        int r = idx >> 4, cc2 = (idx & 15) * 8;
        cpa16(sptr(&Qs[r*FA_DS + cc2]), Qg + (size_t)(qt*FA_BQ + r)*QKVP + cc2, 16);
    }
    cp_commit();

    auto prefKV = [&](int kt, int buf){
        const __half* kb = Kg + (size_t)kt*FA_BK*QKVP;
        const __half* vb = Vg + (size_t)kt*FA_BK*QKVP;
        #pragma unroll
        for (int i = 0; i < 4; i++){
            int idx = tid + i*256;
            int r = idx >> 4, cc2 = (idx & 15) * 8;
            cpa16(sptr(&Ks[(buf*FA_BK + r)*FA_DS + cc2]), kb + (size_t)r*QKVP + cc2, 16);
        }
        #pragma unroll
        for (int i = 0; i < 4; i++){
            int idx = tid + i*256;
            int r = idx >> 4, cc2 = (idx & 15) * 8;
            cpa16(sptr(&Vs[(buf*FA_BK + r)*FA_DS + cc2]), vb + (size_t)r*QKVP + cc2, 16);
        }
    };
    prefKV(0, 0);
    cp_commit();
    cp_wait0();
    __syncthreads();

    // Q fragments: warp's 16 rows, k=128 -> 8 k16 groups
    unsigned qa[8][4];
    #pragma unroll
    for (int kk = 0; kk < 8; kk++){
        unsigned ad = sptr(&Qs[(w*16 + (lane & 15))*FA_DS + kk*16 + (lane >> 4)*8]);
        ldsm4(qa[kk][0], qa[kk][1], qa[kk][2], qa[kk][3], ad);
    }

    float o[16][4];
    #pragma unroll
    for (int i = 0; i < 16; i++){ o[i][0]=0.f; o[i][1]=0.f; o[i][2]=0.f; o[i][3]=0.f; }
    float rs0 = 0.f, rs1 = 0.f;

    for (int kt = 0; kt < TT/FA_BK; kt++){
        int buf = kt & 1;
        if (kt){            // chunk kt arrival (chunk 0 already waited)
            cp_wait0();
            __syncthreads();
        }
        if (kt + 1 < TT/FA_BK) prefKV(kt + 1, buf ^ 1);
        cp_commit();

        // S = Q @ K^T : 64 keys = 8 n8 tiles
        float s[8][4];
        #pragma unroll
        for (int i = 0; i < 8; i++){ s[i][0]=0.f; s[i][1]=0.f; s[i][2]=0.f; s[i][3]=0.f; }
        #pragma unroll
        for (int ks = 0; ks < 8; ks++){
            unsigned kbf[8][2];
            #pragma unroll
            for (int np = 0; np < 4; np++){
                unsigned ad = sptr(&Ks[(buf*FA_BK + np*16 + (lane & 7) + ((lane >> 4) << 3))*FA_DS
                                        + ks*16 + ((lane >> 3) & 1)*8]);
                ldsm4(kbf[np*2][0], kbf[np*2][1], kbf[np*2+1][0], kbf[np*2+1][1], ad);
            }
            #pragma unroll
            for (int nt = 0; nt < 8; nt++)
                mma16816(s[nt], qa[ks], kbf[nt]);
        }

        // p = exp(0.1*s) as fp16; rowsum over half-rounded values; pack A-frags
        unsigned pa[4][4];
        #pragma unroll
        for (int nt = 0; nt < 8; nt++){
            __half2 h01 = __floats2half2_rn(__expf(s[nt][0]*0.1f), __expf(s[nt][1]*0.1f));
            __half2 h23 = __floats2half2_rn(__expf(s[nt][2]*0.1f), __expf(s[nt][3]*0.1f));
            int g = nt >> 1, odd = (nt & 1) << 1;
            pa[g][odd]     = *(unsigned*)&h01;
            pa[g][odd + 1] = *(unsigned*)&h23;
            float2 f01 = __half22float2(h01); rs0 += f01.x + f01.y;
            float2 f23 = __half22float2(h23); rs1 += f23.x + f23.y;
        }

        // O += P @ V : k=64 keys = 4 k16 steps; n=128 d = 16 n8 tiles
        #pragma unroll
        for (int ks = 0; ks < 4; ks++){
            #pragma unroll
            for (int nt16 = 0; nt16 < 8; nt16++){
                unsigned b0[2], b1[2];
                unsigned ad = sptr(&Vs[(buf*FA_BK + ks*16 + (lane & 15))*FA_DS
                                        + nt16*16 + (lane >> 4)*8]);
                ldsm4t(b0[0], b0[1], b1[0], b1[1], ad);
                mma16816(o[nt16*2],     pa[ks], b0);
                mma16816(o[nt16*2 + 1], pa[ks], b1);
            }
        }
        __syncthreads();   // compute done before buf is overwritten next+1 iter
    }

    // reduce rowsums across the 4 lanes sharing a row
    rs0 += __shfl_xor_sync(0xffffffffu, rs0, 1);
    rs0 += __shfl_xor_sync(0xffffffffu, rs0, 2);
    rs1 += __shfl_xor_sync(0xffffffffu, rs1, 1);
    rs1 += __shfl_xor_sync(0xffffffffu, rs1, 2);
    float inv0 = 1.f / rs0, inv1 = 1.f / rs1;

    int row0 = qt*FA_BQ + w*16 + (lane >> 2);
    __half* o0 = att + ((size_t)c*TT + row0)*ATTP + h*DP;
    __half* o1 = o0 + 8*ATTP;
    #pragma unroll
    for (int nt = 0; nt < 16; nt++){
        int col = nt*8 + (lane & 3)*2;
        if (col <= 98){
            *(__half2*)(o0 + col) = __floats2half2_rn(o[nt][0]*inv0, o[nt][1]*inv0);
            *(__half2*)(o1 + col) = __floats2half2_rn(o[nt][2]*inv1, o[nt][3]*inv1);
        }
    }
}

// ---------------- fp16 tensor-core GEMM ----------------
// EPI: 0 half(acc); 3 f32 acc+res; 4 half(relu(acc+bias)); 5 f32 acc+bias+res
#define BM 128
#define BN 64
#define BKK 32

template<int EPI>
__global__ void __launch_bounds__(256)
hgemm(const __half* __restrict__ A, const __half* __restrict__ B,
      float* __restrict__ outF, __half* __restrict__ outH,
      const float* __restrict__ bias, const float* __restrict__ res, int ldr,
      int M, int N, int K, int lda, int ldb, int ldc)
{
    __shared__ __align__(16) __half As[2][BM][BKK+8];
    __shared__ __align__(16) __half Bs[2][BKK][BN+8];

    int tid = threadIdx.x;
    int m0 = blockIdx.y * BM, n0 = blockIdx.x * BN;
    int warp = tid >> 5, lane = tid & 31;
    int wm0 = (warp >> 1) * 32, wn0 = (warp & 1) * 32;

    float c[2][4][4];
    #pragma unroll
    for (int a=0;a<2;a++) for (int b=0;b<4;b++) for (int d=0;d<4;d++) c[a][b][d]=0.f;

    auto prefA = [&](int kt, int buf){
        int k0 = kt*BKK;
        #pragma unroll
        for (int i=0;i<2;i++){
            int q = tid + i*256;
            int r = q >> 2, cc = (q & 3) * 8;
            cpa16(sptr(&As[buf][r][cc]), A + (size_t)(m0+r)*lda + k0 + cc, 16);
        }
    };
    auto prefB = [&](int kt, int buf){
        int k0 = kt*BKK;
        int r = tid >> 3, cc = (tid & 7) * 8;
        int nrem = N - (n0 + cc);
        int bytes = nrem >= 8 ? 16 : (nrem > 0 ? nrem*2 : 0);
        const __half* src = bytes ? (B + (size_t)(k0+r)*ldb + n0 + cc) : B;
        cpa16(sptr(&Bs[buf][r][cc]), src, bytes);
    };

    int nk = K / BKK;
    prefA(0,0); prefB(0,0); cp_commit();

    for (int kt = 0; kt < nk; kt++){
        int buf = kt & 1;
        cp_wait0();
        __syncthreads();
        if (kt+1 < nk){ prefA(kt+1, buf^1); prefB(kt+1, buf^1); }
        cp_commit();

        #pragma unroll
        for (int ks = 0; ks < 2; ks++){
            unsigned a[2][4], b[4][2];
            #pragma unroll
            for (int mt = 0; mt < 2; mt++){
                unsigned ad = sptr(&As[buf][wm0 + mt*16 + (lane & 15)][ks*16 + (lane >> 4)*8]);
                ldsm4(a[mt][0], a[mt][1], a[mt][2], a[mt][3], ad);
            }
            #pragma unroll
            for (int np = 0; np < 2; np++){
                unsigned ad = sptr(&Bs[buf][ks*16 + (lane & 15)][wn0 + np*16 + (lane >> 4)*8]);
                ldsm4t(b[np*2][0], b[np*2][1], b[np*2+1][0], b[np*2+1][1], ad);
            }
            #pragma unroll
            for (int mt = 0; mt < 2; mt++)
                #pragma unroll
                for (int nt = 0; nt < 4; nt++)
                    mma16816(c[mt][nt], a[mt], b[nt]);
        }
        __syncthreads();
    }

    #pragma unroll
    for (int mt = 0; mt < 2; mt++){
        #pragma unroll
        for (int i = 0; i < 2; i++){
            int row = m0 + wm0 + mt*16 + (lane >> 2) + i*8;
            #pragma unroll
            for (int nt = 0; nt < 4; nt++){
                int col = n0 + wn0 + nt*8 + (lane & 3)*2;
                if (col >= N) continue;
                float v0 = c[mt][nt][i*2+0];
                float v1 = c[mt][nt][i*2+1];
                size_t off = (size_t)row*ldc + col;
                if (EPI == 0){
                    *(__half2*)(outH + off) = __floats2half2_rn(v0, v1);
                } else if (EPI == 3){
                    outF[off]   = v0 + res[(size_t)row*ldr + col];
                    outF[off+1] = v1 + res[(size_t)row*ldr + col + 1];
                } else if (EPI == 4){
                    *(__half2*)(outH + off) = __floats2half2_rn(fmaxf(v0 + bias[col], 0.f),
                                                                fmaxf(v1 + bias[col+1], 0.f));
                } else if (EPI == 5){
                    outF[off]   = v0 + bias[col]   + res[(size_t)row*ldr + col];
                    outF[off+1] = v1 + bias[col+1] + res[(size_t)row*ldr + col + 1];
                }
            }
        }
    }
}

// ---------------- conversions / packing ----------------
__global__ void k_h16(const float* __restrict__ x, __half* __restrict__ xh){
    int idx = blockIdx.x*256 + threadIdx.x;
    if (idx >= CT*DP) return;
    int row = idx / DP, col = idx % DP;
    xh[idx] = __float2half(col < DD ? x[row*DD + col] : 0.f);
}

__global__ void k_pack_qkv(const float* __restrict__ wq, const float* __restrict__ wk,
                           const float* __restrict__ wv){
    int idx = blockIdx.x*256 + threadIdx.x;
    if (idx >= NLAYER*DP*QKVP) return;
    int l = idx / (DP*QKVP);
    int r = idx % (DP*QKVP);
    int k = r / QKVP, n = r % QKVP;
    int slot = n / DP, d = n % DP;
    int type = slot / HH, h = slot % HH;
    float v = 0.f;
    if (k < DD && d < DD){
        const float* w = type == 0 ? wq : (type == 1 ? wk : wv);
        v = w[(((size_t)l*HH + h)*DD + k)*DD + d];
    }
    g_wqkv[idx] = __float2half(v);
}

__global__ void k_pack_wm(const float* __restrict__ wm){
    int idx = blockIdx.x*256 + threadIdx.x;
    if (idx >= NLAYER*ATTP*DP) return;
    int l = idx / (ATTP*DP);
    int r = idx % (ATTP*DP);
    int k = r / DP, n = r % DP;
    int h = k / DP, dk = k % DP;
    float v = 0.f;
    if (dk < DD && n < DD)
        v = wm[((size_t)l*(HH*DD) + h*DD + dk)*DD + n];
    g_wm[idx] = __float2half(v);
}

__global__ void k_pack_f1(const float* __restrict__ f1){
    int idx = blockIdx.x*256 + threadIdx.x;
    if (idx >= NLAYER*DP*FFND) return;
    int l = idx / (DP*FFND);
    int r = idx % (DP*FFND);
    int k = r / FFND, n = r % FFND;
    g_f1[idx] = __float2half(k < DD ? f1[((size_t)l*DD + k)*FFND + n] : 0.f);
}

__global__ void k_pack_f2(const float* __restrict__ f2){
    int idx = blockIdx.x*256 + threadIdx.x;
    if (idx >= NLAYER*FFND*DP) return;
    int l = idx / (FFND*DP);
    int r = idx % (FFND*DP);
    int k = r / DP, n = r % DP;
    g_f2[idx] = __float2half(n < DD ? f2[((size_t)l*FFND + k)*DD + n] : 0.f);
}

// ---------------- layernorm (fp32 in-place) + fp16 padded output ----------------
__global__ void k_lnh(float* __restrict__ x, const float* __restrict__ g,
                      const float* __restrict__ b, __half* __restrict__ xh){
    int warp = threadIdx.x >> 5;
    int lane = threadIdx.x & 31;
    int row = blockIdx.x*8 + warp;
    if (row >= CT) return;
    float* xr = x + (size_t)row*DD;
    float v0 = xr[lane], v1 = xr[lane+32], v2 = xr[lane+64];
    float v3 = (lane + 96 < DD) ? xr[lane+96] : 0.f;
    float s = v0 + v1 + v2 + v3;
    #pragma unroll
    for (int o = 16; o; o >>= 1) s += __shfl_xor_sync(0xffffffffu, s, o);
    float mean = s * (1.f/DD);
    float d0 = v0-mean, d1 = v1-mean, d2 = v2-mean;
    float d3 = (lane + 96 < DD) ? (v3 - mean) : 0.f;
    float vs = d0*d0 + d1*d1 + d2*d2 + d3*d3;
    #pragma unroll
    for (int o = 16; o; o >>= 1) vs += __shfl_xor_sync(0xffffffffu, vs, o);
    float inv = rsqrtf(vs * (1.f/DD) + 1e-5f);
    __half* hr = xh + (size_t)row*DP;
    float w;
    w = d0*inv*g[lane]    + b[lane];    xr[lane]    = w; hr[lane]    = __float2half(w);
    w = d1*inv*g[lane+32] + b[lane+32]; xr[lane+32] = w; hr[lane+32] = __float2half(w);
    w = d2*inv*g[lane+64] + b[lane+64]; xr[lane+64] = w; hr[lane+64] = __float2half(w);
    if (lane + 96 < DD){
        w = d3*inv*g[lane+96] + b[lane+96]; xr[lane+96] = w; hr[lane+96] = __float2half(w);
    } else {
        hr[96 + lane] = __half(0.f);
    }
}

// ---------------- GCN (fp32, cheap) ----------------
__global__ void k_adj(const float* __restrict__ A){
    int i = threadIdx.x;
    if (i >= CC) return;
    float s = 0.f;
    for (int j = 0; j < CC; j++) s += A[i*CC + j] + (i == j ? 1.f : 0.f);
    float inv = 1.f / s;
    for (int j = 0; j < CC; j++)
        g_adj[i*CC + j] = (A[i*CC + j] + (i == j ? 1.f : 0.f)) * inv;
}

__global__ void k_agg(const float* __restrict__ in, float* __restrict__ out, int TD){
    int n = blockIdx.x * blockDim.x + threadIdx.x;
    int i = blockIdx.y;
    if (n >= TD) return;
    float acc = 0.f;
    #pragma unroll
    for (int j = 0; j < CC; j++)
        acc += g_adj[i*CC + j] * in[(size_t)j*TD + n];
    out[(size_t)i*TD + n] = acc;
}

template<int RELU, int HASB>
__global__ void __launch_bounds__(256)
k_gemm(const float* __restrict__ A, const float* __restrict__ B,
       const float* __restrict__ bias, float* __restrict__ C, int M, int N, int K){
    __shared__ __align__(16) float As[16][64];
    __shared__ __align__(16) float Bs[16][64];
    int tid = threadIdx.x;
    int tx = tid & 15, ty = tid >> 4;
    int m0 = blockIdx.y * 64, n0 = blockIdx.x * 64;
    float acc[4][4] = {};
    int nk = (K + 15) >> 4;
    for (int kt = 0; kt < nk; kt++){
        int k0 = kt * 16;
        {
            int r = tid >> 2; int kc = (tid & 3) * 4;
            int grow = m0 + r;
            #pragma unroll
            for (int i = 0; i < 4; i++){
                int kk = k0 + kc + i;
                As[kc + i][r] = (grow < M && kk < K) ? A[(size_t)grow*K + kk] : 0.f;
            }
        }
        {
            int kr = tid >> 4; int nc = (tid & 15) * 4;
            int gk = k0 + kr;
            #pragma unroll
            for (int i = 0; i < 4; i++){
                int gn = n0 + nc + i;
                Bs[kr][nc + i] = (gk < K && gn < N) ? B[(size_t)gk*N + gn] : 0.f;
            }
        }
        __syncthreads();
        #pragma unroll
        for (int kc = 0; kc < 16; kc++){
            float4 a4 = *(const float4*)&As[kc][ty*4];
            float4 b4 = *(const float4*)&Bs[kc][tx*4];
            float av[4] = {a4.x, a4.y, a4.z, a4.w};
            float bv[4] = {b4.x, b4.y, b4.z, b4.w};
            #pragma unroll
            for (int j = 0; j < 4; j++)
                #pragma unroll
                for (int i = 0; i < 4; i++)
                    acc[j][i] += av[j] * bv[i];
        }
        __syncthreads();
    }
    #pragma unroll
    for (int j = 0; j < 4; j++){
        int row = m0 + ty*4 + j;
        if (row >= M) continue;
        #pragma unroll
        for (int i = 0; i < 4; i++){
            int col = n0 + tx*4 + i;
            if (col >= N) continue;
            float v = acc[j][i];
            if (HASB) v += bias[col];
            if (RELU) v = fmaxf(v, 0.f);
            C[(size_t)row*N + col] = v;
        }
    }
}

// ---------------- prediction head ----------------
__global__ void k_stepM(const float* __restrict__ l1, const float* __restrict__ l1b,
                        const float* __restrict__ l2, const float* __restrict__ l2b){
    int idx = blockIdx.x * blockDim.x + threadIdx.x;
    if (idx < DD*DD){
        int e = idx / DD, d = idx % DD;
        float acc = 0.f;
        for (int r = 0; r < LHID; r++)
            acc += l1[e*LHID + r] * l2[r*DD + d];
        g_M2[idx] = acc;
    } else if (idx < DD*DD + DD){
        int d = idx - DD*DD;
        float acc = l2b[d];
        for (int r = 0; r < LHID; r++)
            acc += l1b[r] * l2[r*DD + d];
        g_cvec[d] = acc;
    }
}

__global__ void k_step(const float* __restrict__ carry, int rstride,
                       float* __restrict__ out, float* __restrict__ nxt, int kidx){
    int idx = blockIdx.x * blockDim.x + threadIdx.x;
    if (idx >= CC*DD) return;
    int c = idx / DD, d = idx % DD;
    const float* cr = carry + (size_t)c*rstride;
    float acc = g_cvec[d];
    #pragma unroll 4
    for (int e = 0; e < DD; e++)
        acc += cr[e] * g_M2[e*DD + d];
    out[((size_t)c*NPREDK + kidx)*DD + d] = acc;
    nxt[c*DD + d] = acc;
}

// ---------------- host orchestration ----------------
static float* symF(const void* s){ void* p = nullptr; cudaGetSymbolAddress(&p, s); return (float*)p; }
static __half* symH(const void* s){ void* p = nullptr; cudaGetSymbolAddress(&p, s); return (__half*)p; }

extern "C" void kernel_launch(void* const* d_in, const int* in_sizes, int n_in,
                              void* d_out, int out_size){
    const float* X      = (const float*)d_in[0];
    const float* A      = (const float*)d_in[1];
    const float* gcn_w1 = (const float*)d_in[2];
    const float* gcn_b1 = (const float*)d_in[3];
    const float* gcn_w2 = (const float*)d_in[4];
    const float* gcn_b2 = (const float*)d_in[5];
    const float* enc_wq = (const float*)d_in[6];
    const float* enc_wk = (const float*)d_in[7];
    const float* enc_wv = (const float*)d_in[8];
    const float* enc_wm = (const float*)d_in[9];
    const float* enc_f1w= (const float*)d_in[10];
    const float* enc_f1b= (const float*)d_in[11];
    const float* enc_f2w= (const float*)d_in[12];
    const float* enc_f2b= (const float*)d_in[13];
    const float* ln1g   = (const float*)d_in[14];
    const float* ln1b   = (const float*)d_in[15];
    const float* ln2g   = (const float*)d_in[16];
    const float* ln2b   = (const float*)d_in[17];
    const float* lin1_w = (const float*)d_in[18];
    const float* lin1_b = (const float*)d_in[19];
    const float* lin2_w = (const float*)d_in[20];
    const float* lin2_b = (const float*)d_in[21];
    float* out = (float*)d_out;

    float*  p_h1   = symF(g_h1);
    float*  p_hid  = symF(g_hid);
    float*  p_hid2 = symF(g_hid2);
    float*  p_x    = symF(g_x);
    float*  p_y    = symF(g_y);
    float*  p_cA   = symF(g_carryA);
    float*  p_cB   = symF(g_carryB);
    __half* p_xh   = symH(g_xh);
    __half* p_qkv  = symH(g_qkvh);
    __half* p_att  = symH(g_atth);
    __half* p_ffn  = symH(g_ffnh);
    __half* p_wqkv = symH(g_wqkv);
    __half* p_wm   = symH(g_wm);
    __half* p_f1   = symH(g_f1);
    __half* p_f2   = symH(g_f2);

    cudaFuncSetAttribute(k_fattn, cudaFuncAttributeMaxDynamicSharedMemorySize, FA_SMEM);

    // GCN (fp32)
    k_adj<<<1, 32>>>(A);
    k_agg<<<dim3((TT*DD + 255)/256, CC), 256>>>(X, p_h1, TT*DD);
    k_gemm<1,1><<<dim3(1, CT/64), 256>>>(p_h1, gcn_w1, gcn_b1, p_hid, CT, HIDG, DD);
    k_agg<<<dim3((TT*HIDG + 255)/256, CC), 256>>>(p_hid, p_hid2, TT*HIDG);
    k_gemm<0,1><<<dim3(2, CT/64), 256>>>(p_hid2, gcn_w2, gcn_b2, p_x, CT, DD, HIDG);

    // pack all weights fp16 (all layers)
    k_pack_qkv<<<(NLAYER*DP*QKVP + 255)/256, 256>>>(enc_wq, enc_wk, enc_wv);
    k_pack_wm <<<(NLAYER*ATTP*DP + 255)/256, 256>>>(enc_wm);
    k_pack_f1 <<<(NLAYER*DP*FFND + 255)/256, 256>>>(enc_f1w);
    k_pack_f2 <<<(NLAYER*FFND*DP + 255)/256, 256>>>(enc_f2w);

    k_h16<<<(CT*DP + 255)/256, 256>>>(p_x, p_xh);

    for (int l = 0; l < NLAYER; l++){
        // QKV: [CT,128] @ [128,1920] -> fp16
        hgemm<0><<<dim3(QKVP/BN, CT/BM), 256>>>(
            p_xh, p_wqkv + (size_t)l*DP*QKVP, nullptr, p_qkv, nullptr, nullptr, 0,
            CT, QKVP, DP, DP, QKVP, QKVP);

        // fused attention: softmax(QK^T/10)V -> fp16 att
        k_fattn<<<dim3(TT/FA_BQ, NB), 256, FA_SMEM>>>(p_qkv, p_att);

        // proj: y = x + att @ wm  (fp32 out)
        hgemm<3><<<dim3(2, CT/BM), 256>>>(
            p_att, p_wm + (size_t)l*ATTP*DP, p_y, nullptr, nullptr, p_x, DD,
            CT, DD, ATTP, ATTP, DP, DD);

        k_lnh<<<CT/8, 256>>>(p_y, ln1g + l*DD, ln1b + l*DD, p_xh);

        // ffn1: relu(xh @ f1 + b1) -> fp16
        hgemm<4><<<dim3(1, CT/BM), 256>>>(
            p_xh, p_f1 + (size_t)l*DP*FFND, nullptr, p_ffn, enc_f1b + l*FFND, nullptr, 0,
            CT, FFND, DP, DP, FFND, FFND);

        // ffn2: x = y + ffn @ f2 + b2 (fp32 out)
        hgemm<5><<<dim3(2, CT/BM), 256>>>(
            p_ffn, p_f2 + (size_t)l*FFND*DP, p_x, nullptr, enc_f2b + l*DD, p_y, DD,
            CT, DD, FFND, FFND, DP, DD);

        k_lnh<<<CT/8, 256>>>(p_x, ln2g + l*DD, ln2b + l*DD, p_xh);
    }

    // head: fold affine chain, iterate
    k_stepM<<<(DD*DD + DD + 255)/256, 256>>>(lin1_w, lin1_b, lin2_w, lin2_b);
    const float* carry = p_x + (size_t)(TT - 1)*DD;
    int rs = TT*DD;
    for (int k = 0; k < NPREDK; k++){
        float* nxt = (k & 1) ? p_cB : p_cA;
        k_step<<<(CC*DD + 255)/256, 256>>>(carry, rs, out, nxt, k);
        carry = nxt;
        rs = DD;
    }
}